// round 14
// baseline (speedup 1.0000x reference)
#include <cuda_runtime.h>
#include <cuda_fp16.h>
#include <math.h>
#include <stdint.h>

#define NN 50000
#define EE 600000
#define DD 128
#define HH 8
// SCALE = sqrt(DH) = 4 -> multiply by 0.25f

// -------------------- scratch (device globals; no allocation) --------------------
__device__ __half g_Qh[(size_t)NN * DD];
__device__ __half g_Kh[(size_t)NN * DD];
__device__ __half g_Vh[(size_t)NN * DD];
__device__ __half g_xh[(size_t)NN * DD];     // A operand (x, later attn-out)
__device__ __half g_wh[4 * DD * DD];         // W^T fp16: [mat][n][k]
__device__ int   g_counts[NN];
__device__ int   g_pos[EE];
__device__ int   g_rowstart[NN + 1];
__device__ int   g_bsum[64];
__device__ int   g_bscan[64];
__device__ int2  g_edges[EE];                // {col, ea bits} grouped by row
__device__ int   g_is64;

// -------------------- helpers --------------------
__device__ __forceinline__ uint32_t smem_u32(const void* p) {
    uint32_t a;
    asm("{ .reg .u64 t; cvta.to.shared.u64 t, %1; cvt.u32.u64 %0, t; }" : "=r"(a) : "l"(p));
    return a;
}
__device__ __forceinline__ int load_idx(const void* ei, int is64, int pos) {
    if (is64) return (int)((const long long*)ei)[pos];
    return ((const int*)ei)[pos];
}
__device__ __forceinline__ void ldsm_x4(uint32_t& r0, uint32_t& r1, uint32_t& r2, uint32_t& r3,
                                        uint32_t addr) {
    asm volatile("ldmatrix.sync.aligned.m8n8.x4.shared.b16 {%0,%1,%2,%3}, [%4];"
                 : "=r"(r0), "=r"(r1), "=r"(r2), "=r"(r3) : "r"(addr));
}
__device__ __forceinline__ void ldsm_x2(uint32_t& r0, uint32_t& r1, uint32_t addr) {
    asm volatile("ldmatrix.sync.aligned.m8n8.x2.shared.b16 {%0,%1}, [%2];"
                 : "=r"(r0), "=r"(r1) : "r"(addr));
}
__device__ __forceinline__ void mma16816h(float* d, const uint32_t* a, const uint32_t* b) {
    asm volatile("mma.sync.aligned.m16n8k16.row.col.f32.f16.f16.f32 "
                 "{%0,%1,%2,%3}, {%4,%5,%6,%7}, {%8,%9}, {%0,%1,%2,%3};"
                 : "+f"(d[0]), "+f"(d[1]), "+f"(d[2]), "+f"(d[3])
                 : "r"(a[0]), "r"(a[1]), "r"(a[2]), "r"(a[3]), "r"(b[0]), "r"(b[1]));
}

// -------------------- probe dtype + zero counts --------------------
__global__ void probe_zero(const void* ei) {
    int i = blockIdx.x * blockDim.x + threadIdx.x;
    if (i == 0) {
        const long long* p = (const long long*)ei;
        int ok = 1;
        for (int t = 0; t < 64; t++) {
            long long v = p[t];
            if (v < 0 || v >= NN) { ok = 0; break; }
        }
        g_is64 = ok;
    }
    if (i < NN) g_counts[i] = 0;
}

// -------------------- CSR build --------------------
__global__ void hist_kernel(const void* __restrict__ ei) {
    int e = blockIdx.x * blockDim.x + threadIdx.x;
    if (e >= EE) return;
    int row = load_idx(ei, g_is64, e);
    g_pos[e] = atomicAdd(&g_counts[row], 1);
}

__global__ __launch_bounds__(1024) void scan1_kernel() {
    __shared__ int s[1024];
    int tid = threadIdx.x;
    int gid = blockIdx.x * 1024 + tid;
    int v = (gid < NN) ? g_counts[gid] : 0;
    s[tid] = v;
    __syncthreads();
#pragma unroll
    for (int off = 1; off < 1024; off <<= 1) {
        int t = (tid >= off) ? s[tid - off] : 0;
        __syncthreads();
        s[tid] += t;
        __syncthreads();
    }
    if (gid < NN) g_rowstart[gid] = s[tid] - v;    // exclusive within block
    if (tid == 1023) g_bsum[blockIdx.x] = s[1023];
}

__global__ void scan2_kernel() {
    __shared__ int s[64];
    int tid = threadIdx.x;
    int v = (tid < 49) ? g_bsum[tid] : 0;
    s[tid] = v;
    __syncthreads();
#pragma unroll
    for (int off = 1; off < 64; off <<= 1) {
        int t = (tid >= off) ? s[tid - off] : 0;
        __syncthreads();
        s[tid] += t;
        __syncthreads();
    }
    g_bscan[tid] = s[tid] - v;
}

__global__ void scan3_kernel() {
    int i = blockIdx.x * blockDim.x + threadIdx.x;
    if (i < NN) g_rowstart[i] += g_bscan[i >> 10];
    if (i == 0) g_rowstart[NN] = EE;
}

__global__ void scatter_kernel(const void* __restrict__ ei, const float* __restrict__ ea) {
    int e = blockIdx.x * blockDim.x + threadIdx.x;
    if (e >= EE) return;
    int is64 = g_is64;
    int row = load_idx(ei, is64, e);
    int col = load_idx(ei, is64, EE + e);
    int idx = g_rowstart[row] + g_pos[e];
    g_edges[idx] = make_int2(col, __float_as_int(ea[e]));
}

// -------------------- fp32 -> fp16 conversions --------------------
__global__ void convert_x(const float* __restrict__ x) {
    int i = blockIdx.x * blockDim.x + threadIdx.x;
    if (i >= NN * DD) return;
    g_xh[i] = __float2half_rn(x[i]);
}

__global__ void convert_w(const float* __restrict__ W0, const float* __restrict__ W1,
                          const float* __restrict__ W2, const float* __restrict__ W3) {
    int i = blockIdx.x * blockDim.x + threadIdx.x;
    if (i >= 4 * DD * DD) return;
    int w = i >> 14;
    int n = (i >> 7) & 127;
    int k = i & 127;
    const float* W = (w == 0) ? W0 : (w == 1) ? W1 : (w == 2) ? W2 : W3;
    g_wh[i] = __float2half_rn(W[k * DD + n]);    // transpose: B[n][k] = W[k][n]
}

// -------------------- fp16 HMMA GEMM: C = A @ W^T + bias --------------------
// CTA tile 128(M) x 128(N) x 128(K), single fp16 chain. 8 warps (2x4), 64x32 each.
#define LDA 136
#define TILE_ELEMS (128 * LDA)                 // halves
#define SME_BIAS_OFF (2 * TILE_ELEMS)
#define SME_TOT (2 * TILE_ELEMS * 2 + 512)     // ~70 KB

__global__ __launch_bounds__(256, 2)
void tgemm(const __half* __restrict__ A,
           const float* __restrict__ b0v, const float* __restrict__ b1v,
           const float* __restrict__ b2v,
           float* __restrict__ Cf, int fused)
{
    extern __shared__ __half sm[];
    __half* sA = sm;
    __half* sB = sm + TILE_ELEMS;
    float* sbias = (float*)(sm + SME_BIAS_OFF);

    const int mat  = fused ? blockIdx.y : 3;
    const __half* B = g_wh + (size_t)mat * DD * DD;
    const float* bias = fused ? (blockIdx.y == 0 ? b0v : blockIdx.y == 1 ? b1v : b2v) : b0v;
    __half* Ch = fused ? (blockIdx.y == 0 ? g_Qh : blockIdx.y == 1 ? g_Kh : g_Vh) : nullptr;

    const int tid  = threadIdx.x;
    const int row0 = blockIdx.x * 128;

    const uint4 zero4 = make_uint4(0, 0, 0, 0);
#pragma unroll
    for (int t = tid; t < 2048; t += 256) {
        int r  = t >> 4;
        int c8 = (t & 15) << 3;
        bool aok = (row0 + r) < NN;
        uint4 va = aok ? *(const uint4*)(A + (size_t)(row0 + r) * DD + c8) : zero4;
        *(uint4*)(sA + r * LDA + c8) = va;
        uint4 wb = *(const uint4*)(B + (size_t)r * DD + c8);
        *(uint4*)(sB + r * LDA + c8) = wb;
    }
    if (tid < 128) sbias[tid] = bias[tid];
    __syncthreads();

    const int wid  = tid >> 5;
    const int lane = tid & 31;
    const int wm = (wid >> 2) * 64;
    const int wn = (wid & 3) * 32;

    const int sub = lane >> 3;
    const int r8  = lane & 7;
    const int aRow = r8 + (sub & 1) * 8;
    const int aKof = (sub >> 1) * 8;
    const int bl  = lane & 15;
    const int bRow = bl & 7;
    const int bKof = (bl >> 3) * 8;

    const uint32_t smb = smem_u32(sm);
    const uint32_t aB = smb;
    const uint32_t bB = smb + TILE_ELEMS * 2;

    float acc[4][4][4];
#pragma unroll
    for (int mt = 0; mt < 4; mt++)
#pragma unroll
        for (int nt = 0; nt < 4; nt++)
#pragma unroll
            for (int j = 0; j < 4; j++) acc[mt][nt][j] = 0.0f;

#pragma unroll
    for (int ks = 0; ks < 8; ks++) {
        const int k0 = ks * 16;
        uint32_t bf[4][2];
#pragma unroll
        for (int nt = 0; nt < 4; nt++) {
            uint32_t off = (uint32_t)((wn + nt * 8 + bRow) * LDA + k0 + bKof) * 2;
            ldsm_x2(bf[nt][0], bf[nt][1], bB + off);
        }
        uint32_t af[4][4];
#pragma unroll
        for (int mt = 0; mt < 4; mt++) {
            uint32_t off = (uint32_t)((wm + mt * 16 + aRow) * LDA + k0 + aKof) * 2;
            ldsm_x4(af[mt][0], af[mt][1], af[mt][2], af[mt][3], aB + off);
        }
#pragma unroll
        for (int mt = 0; mt < 4; mt++)
#pragma unroll
            for (int nt = 0; nt < 4; nt++)
                mma16816h(acc[mt][nt], af[mt], bf[nt]);
    }

    const int g  = lane >> 2;
    const int t4 = lane & 3;
#pragma unroll
    for (int mt = 0; mt < 4; mt++) {
#pragma unroll
        for (int nt = 0; nt < 4; nt++) {
            int col = wn + nt * 8 + t4 * 2;
            float b0 = sbias[col], b1 = sbias[col + 1];
            int gr0 = row0 + wm + mt * 16 + g;
            int gr1 = gr0 + 8;
            if (fused) {
                if (gr0 < NN)
                    *(__half2*)(Ch + (size_t)gr0 * DD + col) =
                        __floats2half2_rn(acc[mt][nt][0] + b0, acc[mt][nt][1] + b1);
                if (gr1 < NN)
                    *(__half2*)(Ch + (size_t)gr1 * DD + col) =
                        __floats2half2_rn(acc[mt][nt][2] + b0, acc[mt][nt][3] + b1);
            } else {
                if (gr0 < NN)
                    *(float2*)(Cf + (size_t)gr0 * DD + col) =
                        make_float2(acc[mt][nt][0] + b0, acc[mt][nt][1] + b1);
                if (gr1 < NN)
                    *(float2*)(Cf + (size_t)gr1 * DD + col) =
                        make_float2(acc[mt][nt][2] + b0, acc[mt][nt][3] + b1);
            }
        }
    }
}

// -------------------- node pass: warp per node, register accumulation --------
// out[n] = sum_e exp(score_e) * V[col_e] / (sum_e exp(score_e) + 1e-8)
// fp16 Q/K/V gathers; prefetches the next edge record to overlap L2 latency.
__global__ __launch_bounds__(256)
void node_pass()
{
    int n = (int)((blockIdx.x * (unsigned)blockDim.x + threadIdx.x) >> 5);
    if (n >= NN) return;
    const int lane = threadIdx.x & 31;

    const int beg = g_rowstart[n];
    const int end = g_rowstart[n + 1];

    uint2 qp = *(const uint2*)(g_Qh + (size_t)n * DD + lane * 4);
    float2 q01 = __half22float2(*(__half2*)&qp.x);
    float2 q23 = __half22float2(*(__half2*)&qp.y);

    float4 accv = make_float4(0.f, 0.f, 0.f, 0.f);
    float  ssum = 0.0f;

    int2 nxt = (beg < end) ? g_edges[beg] : make_int2(0, 0);
    for (int i = beg; i < end; i++) {
        int2 epk = nxt;
        if (i + 1 < end) nxt = g_edges[i + 1];     // prefetch next record
        int   c  = epk.x;
        float eav = __int_as_float(epk.y);

        uint2 kp = *(const uint2*)(g_Kh + (size_t)c * DD + lane * 4);
        uint2 vp = *(const uint2*)(g_Vh + (size_t)c * DD + lane * 4);

        float2 k01 = __half22float2(*(__half2*)&kp.x);
        float2 k23 = __half22float2(*(__half2*)&kp.y);
        float d = q01.x * k01.x + q01.y * k01.y + q23.x * k23.x + q23.y * k23.y;
        d += __shfl_xor_sync(0xffffffffu, d, 1);
        d += __shfl_xor_sync(0xffffffffu, d, 2);   // per-head dot (4-lane groups)

        float sexp = __expf(d * 0.25f + eav);
        ssum += sexp;

        float2 v01 = __half22float2(*(__half2*)&vp.x);
        float2 v23 = __half22float2(*(__half2*)&vp.y);
        accv.x += sexp * v01.x;
        accv.y += sexp * v01.y;
        accv.z += sexp * v23.x;
        accv.w += sexp * v23.y;
    }

    const float inv = 1.0f / (ssum + 1e-8f);       // ssum identical within head group
    uint2 o;
    *(__half2*)&o.x = __floats2half2_rn(accv.x * inv, accv.y * inv);
    *(__half2*)&o.y = __floats2half2_rn(accv.z * inv, accv.w * inv);
    *(uint2*)(g_xh + (size_t)n * DD + lane * 4) = o;
}

// -------------------- launch --------------------
extern "C" void kernel_launch(void* const* d_in, const int* in_sizes, int n_in,
                              void* d_out, int out_size)
{
    const float* x  = (const float*)d_in[0];
    const void*  ei = d_in[1];
    const float* ea = (const float*)d_in[2];
    const float* Wq = (const float*)d_in[3];
    const float* bq = (const float*)d_in[4];
    const float* Wk = (const float*)d_in[5];
    const float* bk = (const float*)d_in[6];
    const float* Wv = (const float*)d_in[7];
    const float* bv = (const float*)d_in[8];
    const float* Wo = (const float*)d_in[9];
    const float* bo = (const float*)d_in[10];
    float* out = (float*)d_out;

    static int inited = 0;
    static cudaStream_t s2;
    static cudaEvent_t evFork, evJoin;
    if (!inited) {
        cudaFuncSetAttribute(tgemm, cudaFuncAttributeMaxDynamicSharedMemorySize, SME_TOT);
        cudaStreamCreateWithFlags(&s2, cudaStreamNonBlocking);
        cudaEventCreateWithFlags(&evFork, cudaEventDisableTiming);
        cudaEventCreateWithFlags(&evJoin, cudaEventDisableTiming);
        inited = 1;
    }

    __half* xh;
    cudaGetSymbolAddress((void**)&xh, g_xh);

    const int gemm_blocks = (NN + 127) / 128;

    // ---- fork: CSR build chain on s2, GEMM chain on the main stream ----
    cudaEventRecord(evFork, 0);
    cudaStreamWaitEvent(s2, evFork, 0);

    // chain B (s2): CSR build
    probe_zero<<<(NN + 255) / 256, 256, 0, s2>>>(ei);
    hist_kernel<<<(EE + 255) / 256, 256, 0, s2>>>(ei);
    scan1_kernel<<<49, 1024, 0, s2>>>();
    scan2_kernel<<<1, 64, 0, s2>>>();
    scan3_kernel<<<(NN + 255) / 256, 256, 0, s2>>>();
    scatter_kernel<<<(EE + 255) / 256, 256, 0, s2>>>(ei, ea);
    cudaEventRecord(evJoin, s2);

    // chain A (main): converts + fused Q,K,V projections
    convert_x<<<(NN * DD + 255) / 256, 256>>>(x);
    convert_w<<<(4 * DD * DD + 255) / 256, 256>>>(Wq, Wk, Wv, Wo);
    tgemm<<<dim3(gemm_blocks, 3), 256, SME_TOT>>>(xh, bq, bk, bv, nullptr, 1);

    // ---- join ----
    cudaStreamWaitEvent(0, evJoin, 0);

    // Attention (writes fp16 A operand for final GEMM)
    node_pass<<<(NN * 32 + 255) / 256, 256>>>();

    // Output projection (fp32 out)
    tgemm<<<dim3(gemm_blocks, 1), 256, SME_TOT>>>(xh, bo, nullptr, nullptr, out, 0);
}